// round 16
// baseline (speedup 1.0000x reference)
#include <cuda_runtime.h>
#include <cuda_bf16.h>
#include <cuda_fp16.h>
#include <math.h>
#include <stdint.h>

namespace cfg {
constexpr int B = 4, S = 2048, D = 1024, H = 16, DK = 64;
constexpr long long BSD = (long long)B * S * D;
constexpr long long SS  = (long long)S * S;
}

// ---------------------------------------------------------------------------
// Single-fp16 plane [chunk][row][u], unit stored at u ^ (row & 7).
// ---------------------------------------------------------------------------
__device__ float g_wot[1024 * 1024];
__device__ float g_bo2[1024];

__device__ uint4 g_xq16h[16LL * 8192 * 8];
__device__ uint4 g_xk16h[16LL * 8192 * 8];
__device__ uint4 g_xv16h[16LL * 8192 * 8];
__device__ uint4 g_wq16h[16LL * 1024 * 8];
__device__ uint4 g_wk16h[16LL * 1024 * 8];
__device__ uint4 g_wv16h[16LL * 1024 * 8];
__device__ uint4 g_wot2_16h[16LL * 1024 * 8];
__device__ uint4 g_attn16h[16LL * 8192 * 8];
__device__ uint4 g_q16h[16LL * 8192 * 8];
__device__ uint4 g_k16h[16LL * 8192 * 8];
__device__ uint4 g_vt16h[64LL * 32 * 64 * 8];

// ---------------------------------------------------------------------------
__device__ __forceinline__ uint32_t smem_u32(const void* p) {
    uint32_t a;
    asm("{ .reg .u64 t; cvta.to.shared.u64 t, %1; cvt.u32.u64 %0, t; }"
        : "=r"(a) : "l"(p));
    return a;
}
__device__ __forceinline__ void ldsm_x4(uint32_t addr, uint32_t r[4]) {
    asm volatile("ldmatrix.sync.aligned.m8n8.x4.shared.b16 {%0,%1,%2,%3}, [%4];"
                 : "=r"(r[0]), "=r"(r[1]), "=r"(r[2]), "=r"(r[3]) : "r"(addr));
}
__device__ __forceinline__ void ldsm_x2(uint32_t addr, uint32_t r[2]) {
    asm volatile("ldmatrix.sync.aligned.m8n8.x2.shared.b16 {%0,%1}, [%2];"
                 : "=r"(r[0]), "=r"(r[1]) : "r"(addr));
}
__device__ __forceinline__ void mma_bf16(float* c, const uint32_t* a,
                                         uint32_t b0, uint32_t b1) {
    asm volatile(
        "mma.sync.aligned.m16n8k16.row.col.f32.bf16.bf16.f32 "
        "{%0,%1,%2,%3},{%4,%5,%6,%7},{%8,%9},{%0,%1,%2,%3};"
        : "+f"(c[0]), "+f"(c[1]), "+f"(c[2]), "+f"(c[3])
        : "r"(a[0]), "r"(a[1]), "r"(a[2]), "r"(a[3]), "r"(b0), "r"(b1));
}
__device__ __forceinline__ void mma_fp16(float* c, const uint32_t* a,
                                         uint32_t b0, uint32_t b1) {
    asm volatile(
        "mma.sync.aligned.m16n8k16.row.col.f32.f16.f16.f32 "
        "{%0,%1,%2,%3},{%4,%5,%6,%7},{%8,%9},{%0,%1,%2,%3};"
        : "+f"(c[0]), "+f"(c[1]), "+f"(c[2]), "+f"(c[3])
        : "r"(a[0]), "r"(a[1]), "r"(a[2]), "r"(a[3]), "r"(b0), "r"(b1));
}
__device__ __forceinline__ void cp16(uint32_t dst, const void* src) {
    asm volatile("cp.async.cg.shared.global [%0], [%1], 16;" :: "r"(dst), "l"(src));
}
__device__ __forceinline__ void cp_commit() {
    asm volatile("cp.async.commit_group;" ::: "memory");
}
template <int N>
__device__ __forceinline__ void cp_wait() {
    asm volatile("cp.async.wait_group %0;" :: "n"(N) : "memory");
}
__device__ __forceinline__ void stg_cs4(float* p, float a, float b, float c, float d) {
    asm volatile("st.global.cs.v4.f32 [%0], {%1,%2,%3,%4};"
                 :: "l"(p), "f"(a), "f"(b), "f"(c), "f"(d) : "memory");
}
#define SWZ(o) ((o) ^ (((o) >> 3) & 0x70))

__device__ __forceinline__ void split2(float a, float b, uint32_t& hi, uint32_t& lo) {
    __nv_bfloat16 ha = __float2bfloat16_rn(a);
    __nv_bfloat16 hb = __float2bfloat16_rn(b);
    __nv_bfloat16 la = __float2bfloat16_rn(a - __bfloat162float(ha));
    __nv_bfloat16 lb = __float2bfloat16_rn(b - __bfloat162float(hb));
    hi = (uint32_t)__bfloat16_as_ushort(ha) | ((uint32_t)__bfloat16_as_ushort(hb) << 16);
    lo = (uint32_t)__bfloat16_as_ushort(la) | ((uint32_t)__bfloat16_as_ushort(lb) << 16);
}
__device__ __forceinline__ uint32_t ph2(float a, float b) {
    __half2 h = __floats2half2_rn(a, b);
    return *reinterpret_cast<uint32_t*>(&h);
}
__device__ __forceinline__ void packh8(const float* v, uint4& o) {
    o.x = ph2(v[0], v[1]); o.y = ph2(v[2], v[3]);
    o.z = ph2(v[4], v[5]); o.w = ph2(v[6], v[7]);
}
__device__ __forceinline__ float2 uph2(uint32_t p) {
    __half2 h = *reinterpret_cast<__half2*>(&p);
    return __half22float2(h);
}

// Split-bf16 MMA (3 terms) over buffer AHI|ALO|BHI|BLO (128x128x64)
__device__ __forceinline__ void mma_buf(uint32_t base, int lane, int wm, int wn,
                                        float (&acc)[4][4][4]) {
    const int lrow = lane & 15, lkh = lane >> 4;
#pragma unroll
    for (int kk = 0; kk < 4; kk++) {
        const int kc = kk * 2 + lkh;
        uint32_t ahi[4][4], alo[4][4];
#pragma unroll
        for (int fm = 0; fm < 4; fm++) {
            uint32_t off = SWZ((uint32_t)((wm * 64 + fm * 16 + lrow) * 128 + kc * 16));
            ldsm_x4(base + off, ahi[fm]);
            ldsm_x4(base + 16384 + off, alo[fm]);
        }
        uint32_t bhi[2][4], blo[2][4];
#pragma unroll
        for (int fp = 0; fp < 2; fp++) {
            uint32_t off = SWZ((uint32_t)((wn * 32 + fp * 16 + lrow) * 128 + kc * 16));
            ldsm_x4(base + 32768 + off, bhi[fp]);
            ldsm_x4(base + 32768 + 16384 + off, blo[fp]);
        }
#pragma unroll
        for (int fm = 0; fm < 4; fm++)
#pragma unroll
            for (int fn = 0; fn < 4; fn++) {
                const int fp = fn >> 1, sel = fn & 1;
                mma_bf16(acc[fm][fn], ahi[fm], bhi[fp][sel], bhi[fp][sel + 2]);
                mma_bf16(acc[fm][fn], ahi[fm], blo[fp][sel], blo[fp][sel + 2]);
                mma_bf16(acc[fm][fn], alo[fm], bhi[fp][sel], bhi[fp][sel + 2]);
            }
    }
}

// Single-fp16 MMA over buffer A(16K)|B(16K) (128x128x64)
__device__ __forceinline__ void mma_buf1h(uint32_t base, int lane, int wm, int wn,
                                          float (&acc)[4][4][4]) {
    const int lrow = lane & 15, lkh = lane >> 4;
#pragma unroll
    for (int kk = 0; kk < 4; kk++) {
        const int kc = kk * 2 + lkh;
        uint32_t a[4][4];
#pragma unroll
        for (int fm = 0; fm < 4; fm++) {
            uint32_t off = SWZ((uint32_t)((wm * 64 + fm * 16 + lrow) * 128 + kc * 16));
            ldsm_x4(base + off, a[fm]);
        }
        uint32_t b[2][4];
#pragma unroll
        for (int fp = 0; fp < 2; fp++) {
            uint32_t off = SWZ((uint32_t)((wn * 32 + fp * 16 + lrow) * 128 + kc * 16));
            ldsm_x4(base + 16384 + off, b[fp]);
        }
#pragma unroll
        for (int fm = 0; fm < 4; fm++)
#pragma unroll
            for (int fn = 0; fn < 4; fn++) {
                const int fp = fn >> 1, sel = fn & 1;
                mma_fp16(acc[fm][fn], a[fm], b[fp][sel], b[fp][sel + 2]);
            }
    }
}

// Single-fp16 MMA over buffer A(8K: 64 rows)|B(16K) (64x128x64)
__device__ __forceinline__ void mma_buf64h(uint32_t base, int lane, int wm, int wn,
                                           float (&acc)[2][4][4]) {
    const int lrow = lane & 15, lkh = lane >> 4;
#pragma unroll
    for (int kk = 0; kk < 4; kk++) {
        const int kc = kk * 2 + lkh;
        uint32_t a[2][4];
#pragma unroll
        for (int fm = 0; fm < 2; fm++) {
            uint32_t off = SWZ((uint32_t)((wm * 32 + fm * 16 + lrow) * 128 + kc * 16));
            ldsm_x4(base + off, a[fm]);
        }
        uint32_t b[2][4];
#pragma unroll
        for (int fp = 0; fp < 2; fp++) {
            uint32_t off = SWZ((uint32_t)((wn * 32 + fp * 16 + lrow) * 128 + kc * 16));
            ldsm_x4(base + 8192 + off, b[fp]);
        }
#pragma unroll
        for (int fm = 0; fm < 2; fm++)
#pragma unroll
            for (int fn = 0; fn < 4; fn++) {
                const int fp = fn >> 1, sel = fn & 1;
                mma_fp16(acc[fm][fn], a[fm], b[fp][sel], b[fp][sel + 2]);
            }
    }
}

// ---------------------------------------------------------------------------
// wot2 = (Wo@Wo)^T via bf16 split from fp32 (exact path); fp16 plane out.
// ---------------------------------------------------------------------------
__global__ __launch_bounds__(256, 1) void gemm_wot2(
    const float* __restrict__ A, const float* __restrict__ Bt,
    uint4* __restrict__ C16h) {
    extern __shared__ __align__(1024) char smem[];
    constexpr int BUFSZ = 65536;
    const uint32_t sb = smem_u32(smem);
    const int tid = threadIdx.x, lane = tid & 31, w = tid >> 5;
    const int wm = w & 1, wn = w >> 1;
    const long long rowBase = (long long)blockIdx.y * 128;
    const int colBase = blockIdx.x * 128;
    float acc[4][4][4] = {};

    const int rA = tid >> 4, qA = tid & 15;
    float4 ra[8], rb[8];
    auto loadAB = [&](int c) {
#pragma unroll
        for (int i = 0; i < 8; i++)
            ra[i] = *(const float4*)(A + (rowBase + rA + i * 16) * 1024 +
                                     c * 64 + qA * 4);
#pragma unroll
        for (int i = 0; i < 8; i++)
            rb[i] = *(const float4*)(Bt + (long long)(colBase + rA + i * 16) * 1024 +
                                     c * 64 + qA * 4);
    };
    auto store = [&](int buf) {
        char* base = smem + buf * BUFSZ;
#pragma unroll
        for (int i = 0; i < 8; i++) {
            uint32_t h01, l01, h23, l23;
            split2(ra[i].x, ra[i].y, h01, l01);
            split2(ra[i].z, ra[i].w, h23, l23);
            uint32_t off = SWZ((uint32_t)((rA + i * 16) * 128 + qA * 8));
            *(uint2*)(base + off) = make_uint2(h01, h23);
            *(uint2*)(base + 16384 + off) = make_uint2(l01, l23);
        }
#pragma unroll
        for (int i = 0; i < 8; i++) {
            uint32_t h01, l01, h23, l23;
            split2(rb[i].x, rb[i].y, h01, l01);
            split2(rb[i].z, rb[i].w, h23, l23);
            uint32_t off = SWZ((uint32_t)((rA + i * 16) * 128 + qA * 8));
            *(uint2*)(base + 32768 + off) = make_uint2(h01, h23);
            *(uint2*)(base + 49152 + off) = make_uint2(l01, l23);
        }
    };
    loadAB(0); store(0);
    __syncthreads();
    for (int c = 0; c < 16; c++) {
        const int b = c & 1;
        if (c + 1 < 16) loadAB(c + 1);
        mma_buf(sb + b * BUFSZ, lane, wm, wn, acc);
        if (c + 1 < 16) store(1 - b);
        __syncthreads();
    }
    __syncthreads();

    float* stage = (float*)smem;  // 128 x 132
    const int rl0 = wm * 64 + (lane >> 2), cl0 = wn * 32 + (lane & 3) * 2;
#pragma unroll
    for (int fm = 0; fm < 4; fm++)
#pragma unroll
        for (int fn = 0; fn < 4; fn++) {
            int r = rl0 + fm * 16, c = cl0 + fn * 8;
            stage[r * 132 + c] = acc[fm][fn][0];
            stage[r * 132 + c + 1] = acc[fm][fn][1];
            stage[(r + 8) * 132 + c] = acc[fm][fn][2];
            stage[(r + 8) * 132 + c + 1] = acc[fm][fn][3];
        }
    __syncthreads();
#pragma unroll
    for (int i = 0; i < 8; i++) {
        int e = tid + i * 256, r = e >> 4, u16 = e & 15;
        float v[8];
#pragma unroll
        for (int j = 0; j < 8; j++) v[j] = stage[r * 132 + u16 * 8 + j];
        uint4 hv;
        packh8(v, hv);
        long long chunk = (colBase >> 6) + (u16 >> 3);
        int uu = (u16 & 7) ^ (r & 7);
        C16h[(chunk * 1024 + rowBase + r) * 8 + uu] = hv;
    }
}

// ---------------------------------------------------------------------------
// Merged QKV GEMM, all single-fp16. op = blockIdx.z. grid(8, 64, 3).
// op 0/1: fp16 plane out; op 2: V^T planes in-epilogue.
// ---------------------------------------------------------------------------
__global__ __launch_bounds__(256, 2) void gemm_qkvh(
    const float* __restrict__ bq, const float* __restrict__ bk,
    const float* __restrict__ bv) {
    extern __shared__ __align__(1024) char smem[];
    constexpr int BUFSZ = 32768;
    const uint32_t sb = smem_u32(smem);
    const int tid = threadIdx.x, lane = tid & 31, w = tid >> 5;
    const int wm = w & 1, wn = w >> 1;
    const int op = blockIdx.z;
    const uint4* A16h = op == 0 ? g_xq16h : (op == 1 ? g_xk16h : g_xv16h);
    const uint4* B16h = op == 0 ? g_wq16h : (op == 1 ? g_wk16h : g_wv16h);
    const float* bias = op == 0 ? bq : (op == 1 ? bk : bv);
    const long long rowBase = (long long)blockIdx.y * 128;
    const int colBase = blockIdx.x * 128;
    float acc[4][4][4] = {};

    auto issue = [&](int c, int buf) {
        uint32_t base = sb + buf * BUFSZ;
#pragma unroll
        for (int i = 0; i < 4; i++) {
            int e = tid + i * 256, r = e >> 3, j = e & 7;
            cp16(base + r * 128 + j * 16,
                 A16h + ((long long)c * 8192 + rowBase + r) * 8 + j);
        }
#pragma unroll
        for (int i = 0; i < 4; i++) {
            int e = tid + i * 256, r = e >> 3, j = e & 7;
            cp16(base + 16384 + r * 128 + j * 16,
                 B16h + ((long long)c * 1024 + colBase + r) * 8 + j);
        }
        cp_commit();
    };
    issue(0, 0);
    issue(1, 1);
    for (int c = 0; c < 16; c++) {
        if (c + 1 < 16) cp_wait<1>(); else cp_wait<0>();
        __syncthreads();
        mma_buf1h(sb + (c % 3) * BUFSZ, lane, wm, wn, acc);
        if (c + 2 < 16) issue(c + 2, (c + 2) % 3);
    }
    __syncthreads();

    float* stage = (float*)smem;  // 128 x 132
    const int rl0 = wm * 64 + (lane >> 2), cl0 = wn * 32 + (lane & 3) * 2;
#pragma unroll
    for (int fm = 0; fm < 4; fm++)
#pragma unroll
        for (int fn = 0; fn < 4; fn++) {
            int r = rl0 + fm * 16, c = cl0 + fn * 8;
            stage[r * 132 + c] = acc[fm][fn][0];
            stage[r * 132 + c + 1] = acc[fm][fn][1];
            stage[(r + 8) * 132 + c] = acc[fm][fn][2];
            stage[(r + 8) * 132 + c + 1] = acc[fm][fn][3];
        }
    __syncthreads();

    if (op != 2) {
        uint4* C16h = op == 0 ? g_q16h : g_k16h;
#pragma unroll
        for (int i = 0; i < 8; i++) {
            int e = tid + i * 256, r = e >> 4, u16 = e & 15;
            int gc = colBase + u16 * 8;
            float v[8];
#pragma unroll
            for (int j = 0; j < 8; j++)
                v[j] = stage[r * 132 + u16 * 8 + j] + bias[gc + j];
            uint4 hv;
            packh8(v, hv);
            long long chunk = (colBase >> 6) + (u16 >> 3);
            int uu = (u16 & 7) ^ (r & 7);
            C16h[(chunk * 8192 + rowBase + r) * 8 + uu] = hv;
        }
    } else {
        const int b = (int)(rowBase >> 11);
        const int scb = ((int)rowBase & 2047) >> 6;
#pragma unroll
        for (int i = 0; i < 8; i++) {
            int e = tid + i * 256;
            int hh = e >> 10, p = (e >> 9) & 1, dk = (e >> 3) & 63, u = e & 7;
            int col = hh * 64 + dk;
            float bb = bias[colBase + col];
            float v[8];
#pragma unroll
            for (int j = 0; j < 8; j++)
                v[j] = stage[(p * 64 + u * 8 + j) * 132 + col] + bb;
            uint4 hv;
            packh8(v, hv);
            long long z = (long long)b * 16 + (colBase >> 6) + hh;
            g_vt16h[((z * 32 + scb + p) * 64 + dk) * 8 + (u ^ (dk & 7))] = hv;
        }
    }
}

// ---------------------------------------------------------------------------
// Single-fp16 GEMM, tile 64x128. grid(8, 128).
// ---------------------------------------------------------------------------
__global__ __launch_bounds__(256, 2) void gemm64h(
    const uint4* __restrict__ A16h, long long rowsA,
    const uint4* __restrict__ B16h, long long rowsB,
    float* __restrict__ C, int ldc, int nch, const float* __restrict__ bias) {
    extern __shared__ __align__(1024) char smem[];
    constexpr int BUFSZ = 24576;
    const uint32_t sb = smem_u32(smem);
    const int tid = threadIdx.x, lane = tid & 31, w = tid >> 5;
    const int wm = w & 1, wn = w >> 1;
    const long long rowBase = (long long)blockIdx.y * 64;
    const int colBase = blockIdx.x * 128;
    float acc[2][4][4] = {};

    auto issue = [&](int c, int buf) {
        uint32_t base = sb + buf * BUFSZ;
#pragma unroll
        for (int i = 0; i < 2; i++) {
            int e = tid + i * 256, r = e >> 3, j = e & 7;
            cp16(base + r * 128 + j * 16,
                 A16h + ((long long)c * rowsA + rowBase + r) * 8 + j);
        }
#pragma unroll
        for (int i = 0; i < 4; i++) {
            int e = tid + i * 256, r = e >> 3, j = e & 7;
            cp16(base + 8192 + r * 128 + j * 16,
                 B16h + ((long long)c * rowsB + colBase + r) * 8 + j);
        }
        cp_commit();
    };
    issue(0, 0);
    issue(1, 1);
    for (int c = 0; c < nch; c++) {
        if (c + 1 < nch) cp_wait<1>(); else cp_wait<0>();
        __syncthreads();
        mma_buf64h(sb + (c % 3) * BUFSZ, lane, wm, wn, acc);
        if (c + 2 < nch) issue(c + 2, (c + 2) % 3);
    }

    const long long erow = rowBase + wm * 32 + (lane >> 2);
    const int ecol = colBase + wn * 32 + (lane & 3) * 2;
#pragma unroll
    for (int fm = 0; fm < 2; fm++)
#pragma unroll
        for (int fn = 0; fn < 4; fn++) {
            int cc = ecol + fn * 8;
            float b0 = bias ? bias[cc] : 0.f;
            float b1 = bias ? bias[cc + 1] : 0.f;
            long long r0 = erow + fm * 16;
            *(float2*)(C + r0 * ldc + cc) =
                make_float2(acc[fm][fn][0] + b0, acc[fm][fn][1] + b1);
            *(float2*)(C + (r0 + 8) * ldc + cc) =
                make_float2(acc[fm][fn][2] + b0, acc[fm][fn][3] + b1);
        }
}

// ---------------------------------------------------------------------------
// Fused attention, 512 threads (16 warps). CTA = 32 Q-rows x 2048 K, one (b,h).
// Scores: each warp owns 8 K-cols. PV: each warp owns 16x8 output tile.
// ---------------------------------------------------------------------------
#define OFF_E 0            // 32 chunks x 32 rows x 128B = 131072
#define OFF_K 131072       // 3 bufs x (K 16384 + V 16384)
#define OFF_SUM 229376     // 16 x 32 floats = 2048
#define OFF_INV 231424     // 32 floats
#define SMEM_FA 231552

__global__ __launch_bounds__(512, 1) void fused_attn(float* __restrict__ attnw) {
    extern __shared__ __align__(1024) char smem[];
    const uint32_t sb = smem_u32(smem);
    const int tid = threadIdx.x, lane = tid & 31, w = tid >> 5;  // w: 0..15
    const int lrow = lane & 15, lkh = lane >> 4;
    const int rb = blockIdx.x, z = blockIdx.y;
    const int b = z >> 4, h = z & 15;
    const long long qrow = (long long)b * 2048 + rb * 32;
    float* abz = attnw + (long long)z * cfg::SS;

    // Q staged through buf0's K area, fragments hoisted (all warps)
    if (tid < 256) {
        int r = tid >> 3, j = tid & 7;
        cp16(sb + OFF_K + r * 128 + j * 16,
             g_q16h + ((long long)h * 8192 + qrow + r) * 8 + j);
    }
    cp_commit();
    cp_wait<0>();
    __syncthreads();
    uint32_t a_q[2][4][4];
#pragma unroll
    for (int kk = 0; kk < 4; kk++)
#pragma unroll
        for (int fm = 0; fm < 2; fm++) {
            uint32_t off = SWZ((uint32_t)((fm * 16 + lrow) * 128 + (kk * 2 + lkh) * 16));
            ldsm_x4(sb + OFF_K + off, a_q[fm][kk]);
        }
    __syncthreads();

    auto issueKV = [&](int c, int buf) {
#pragma unroll
        for (int i = 0; i < 2; i++) {   // K: 128 rows x 8 u = 1024
            int e = tid + i * 512, r = e >> 3, j = e & 7;
            cp16(sb + OFF_K + buf * 32768 + r * 128 + j * 16,
                 g_k16h + ((long long)h * 8192 + (long long)b * 2048 + c * 128 + r) * 8 + j);
        }
#pragma unroll
        for (int i = 0; i < 2; i++) {   // V: 2 sc x 64 rows x 8 u = 1024
            int e = tid + i * 512, sc = e >> 9, r = (e >> 3) & 63, j = e & 7;
            cp16(sb + OFF_K + buf * 32768 + 16384 + sc * 8192 + r * 128 + j * 16,
                 g_vt16h + (((long long)z * 32 + c * 2 + sc) * 64 + r) * 8 + j);
        }
        cp_commit();
    };
    issueKV(0, 0);
    issueKV(1, 1);

    const int wm2 = w & 1, wn2 = w >> 1;   // PV: rows wm2*16, cols wn2*8
    const int brow = lane & 7, bkh = (lane >> 3) & 1;  // x2 ldsm addressing
    float acc_pv[4] = {};
    float rs[2][2] = {};

    for (int c = 0; c < 16; c++) {
        const int buf = c % 3;
        if (c + 1 < 16) cp_wait<1>(); else cp_wait<0>();
        __syncthreads();
        if (c + 2 < 16) issueKV(c + 2, (c + 2) % 3);

        // ---- scores: each warp 32 x 8 (K cols w*8..w*8+8) ----
        float acc_s[2][4] = {};
#pragma unroll
        for (int kk = 0; kk < 4; kk++) {
            uint32_t bk[2];
            uint32_t off = SWZ((uint32_t)((w * 8 + brow) * 128 + (kk * 2 + bkh) * 16));
            ldsm_x2(sb + OFF_K + buf * 32768 + off, bk);
            mma_fp16(acc_s[0], a_q[0][kk], bk[0], bk[1]);
            mma_fp16(acc_s[1], a_q[1][kk], bk[0], bk[1]);
        }

        // ---- exp -> E smem, rowsum ----
#pragma unroll
        for (int fm = 0; fm < 2; fm++) {
            int r0 = fm * 16 + (lane >> 2);
            int col = w * 8 + (lane & 3) * 2;
            float e0 = __expf(acc_s[fm][0] * 0.125f);
            float e1 = __expf(acc_s[fm][1] * 0.125f);
            float e2 = __expf(acc_s[fm][2] * 0.125f);
            float e3 = __expf(acc_s[fm][3] * 0.125f);
            int sub = col >> 6, cu = (col & 63) >> 3, cb = (col & 7) * 2;
            uint32_t bc = OFF_E + (c * 2 + sub) * 4096;
            *(uint32_t*)(smem + bc + r0 * 128 + ((cu ^ (r0 & 7)) << 4) + cb) =
                ph2(e0, e1);
            *(uint32_t*)(smem + bc + (r0 + 8) * 128 +
                         ((cu ^ ((r0 + 8) & 7)) << 4) + cb) = ph2(e2, e3);
            rs[fm][0] += e0 + e1;
            rs[fm][1] += e2 + e3;
        }
        __syncthreads();

        // ---- PV: each warp 16 x 8 tile over 128 k ----
#pragma unroll
        for (int kk2 = 0; kk2 < 8; kk2++) {
            uint32_t ae[4], bv[2];
            int kc = (kk2 & 3) * 2 + lkh;
            uint32_t offa = SWZ((uint32_t)((wm2 * 16 + lrow) * 128 + kc * 16));
            ldsm_x4(sb + OFF_E + (c * 2 + (kk2 >> 2)) * 4096 + offa, ae);
            int kc2 = (kk2 & 3) * 2 + bkh;
            uint32_t offb = SWZ((uint32_t)((wn2 * 8 + brow) * 128 + kc2 * 16));
            ldsm_x2(sb + OFF_K + buf * 32768 + 16384 + (kk2 >> 2) * 8192 + offb, bv);
            mma_fp16(acc_pv, ae, bv[0], bv[1]);
        }
    }

    // ---- rowsum reduce -> inv ----
    float* sums = (float*)(smem + OFF_SUM);
    float* inv_s = (float*)(smem + OFF_INV);
#pragma unroll
    for (int fm = 0; fm < 2; fm++) {
        float s0 = rs[fm][0], s1 = rs[fm][1];
        s0 += __shfl_xor_sync(~0u, s0, 1); s0 += __shfl_xor_sync(~0u, s0, 2);
        s1 += __shfl_xor_sync(~0u, s1, 1); s1 += __shfl_xor_sync(~0u, s1, 2);
        if ((lane & 3) == 0) {
            int r0 = fm * 16 + (lane >> 2);
            sums[w * 32 + r0] = s0;
            sums[w * 32 + r0 + 8] = s1;
        }
    }
    __syncthreads();
    if (tid < 32) {
        float s = 0.f;
#pragma unroll
        for (int i = 0; i < 16; i++) s += sums[i * 32 + tid];
        inv_s[tid] = 1.f / s;
    }
    __syncthreads();

    // ---- scale acc_pv, stage attn tile ----
    {
        int rr = wm2 * 16 + (lane >> 2);
        int cc = wn2 * 8 + (lane & 3) * 2;
        float s0 = inv_s[rr], s1 = inv_s[rr + 8];
        float* stage = (float*)(smem + OFF_K);  // 32 x 68
        stage[rr * 68 + cc] = acc_pv[0] * s0;
        stage[rr * 68 + cc + 1] = acc_pv[1] * s0;
        stage[(rr + 8) * 68 + cc] = acc_pv[2] * s1;
        stage[(rr + 8) * 68 + cc + 1] = acc_pv[3] * s1;
    }
    __syncthreads();

    // ---- normalized fp32 attn_weights (32 x 2048), streaming ----
    {
        int r = tid >> 4;                 // 0..31
        int q = tid & 15, u = q & 7, hf = q >> 3;
        float sc = inv_s[r];
        float* dst_row = abz + (long long)(rb * 32 + r) * 2048;
        uint32_t src_ru = OFF_E + r * 128 + ((u ^ (r & 7)) << 4);
#pragma unroll 4
        for (int cc = hf * 16; cc < hf * 16 + 16; cc++) {
            uint4 hv = *(uint4*)(smem + src_ru + cc * 4096);
            float2 v0 = uph2(hv.x), v1 = uph2(hv.y);
            float2 v2 = uph2(hv.z), v3 = uph2(hv.w);
            float* dst = dst_row + cc * 64 + u * 8;
            stg_cs4(dst, v0.x * sc, v0.y * sc, v1.x * sc, v1.y * sc);
            stg_cs4(dst + 4, v2.x * sc, v2.y * sc, v3.x * sc, v3.y * sc);
        }
    }

    // ---- fp16 attn plane (32 x 64, chunk = h) ----
    if (tid < 256) {
        int r = tid >> 3, u = tid & 7;
        float* stage = (float*)(smem + OFF_K);
        float v[8];
#pragma unroll
        for (int j = 0; j < 8; j++) v[j] = stage[r * 68 + u * 8 + j];
        uint4 hv;
        packh8(v, hv);
        int uu = u ^ (r & 7);
        long long grow = (long long)b * 2048 + rb * 32 + r;
        g_attn16h[((long long)h * 8192 + grow) * 8 + uu] = hv;
    }
}

// ---------------------------------------------------------------------------
// Prep kernels
// ---------------------------------------------------------------------------
__global__ void wconv(const float* __restrict__ Wq, const float* __restrict__ Wk,
                      const float* __restrict__ Wv) {
    __shared__ float t2[128][65];
    const int cc = blockIdx.x, rb = blockIdx.y, op = blockIdx.z;
    const float* W = op == 0 ? Wq : (op == 1 ? Wk : Wv);
    uint4* O = op == 0 ? g_wq16h : (op == 1 ? g_wk16h : g_wv16h);
    const int tid = threadIdx.x;
#pragma unroll
    for (int i = 0; i < 32; i++) {
        int e = tid + i * 256, wr = e >> 7, wc = e & 127;
        t2[wc][wr] = W[(cc * 64 + wr) * 1024 + rb * 128 + wc];
    }
    __syncthreads();
#pragma unroll
    for (int i = 0; i < 4; i++) {
        int e = tid + i * 256, r = e >> 3, u = e & 7;
        float v[8];
#pragma unroll
        for (int j = 0; j < 8; j++) v[j] = t2[r][u * 8 + j];
        uint4 hv;
        packh8(v, hv);
        O[((long long)cc * 1024 + rb * 128 + r) * 8 + (u ^ (r & 7))] = hv;
    }
}

__global__ void convert3(const float* __restrict__ q, const float* __restrict__ k,
                         const float* __restrict__ v) {
    const int chunk = blockIdx.x, op = blockIdx.z;
    const float* X = op == 0 ? q : (op == 1 ? k : v);
    uint4* O = op == 0 ? g_xq16h : (op == 1 ? g_xk16h : g_xv16h);
    const long long rb = (long long)blockIdx.y * 128;
    const int tid = threadIdx.x;
#pragma unroll
    for (int i = 0; i < 4; i++) {
        int e = tid + i * 256, r = e >> 3, u = e & 7;
        const float* src = X + (rb + r) * 1024 + chunk * 64 + u * 8;
        float v8[8];
        *(float4*)(v8) = *(const float4*)(src);
        *(float4*)(v8 + 4) = *(const float4*)(src + 4);
        uint4 hv;
        packh8(v8, hv);
        O[((long long)chunk * 8192 + rb + r) * 8 + (u ^ (r & 7))] = hv;
    }
}

__global__ void transpose_g(const float* __restrict__ in, float* __restrict__ out) {
    __shared__ float tile[32][33];
    const int bx = blockIdx.x * 32, by = blockIdx.y * 32;
    const int tx = threadIdx.x, ty = threadIdx.y;
#pragma unroll
    for (int i = 0; i < 32; i += 8)
        tile[ty + i][tx] = in[(long long)(by + ty + i) * 1024 + bx + tx];
    __syncthreads();
#pragma unroll
    for (int i = 0; i < 32; i += 8)
        out[(long long)(bx + ty + i) * 1024 + by + tx] = tile[tx][ty + i];
}

__global__ void bo2_k(const float* __restrict__ bo, const float* __restrict__ Wo) {
    __shared__ float red[16][32];
    const int j = blockIdx.x * 32 + threadIdx.x;
    const int ty = threadIdx.y;
    float s = 0.f;
#pragma unroll 16
    for (int k = ty * 64; k < ty * 64 + 64; k++)
        s += bo[k] * Wo[k * 1024 + j];
    red[ty][threadIdx.x] = s;
    __syncthreads();
    if (ty == 0) {
        float t = bo[j];
#pragma unroll
        for (int i = 0; i < 16; i++) t += red[i][threadIdx.x];
        g_bo2[j] = t;
    }
}

extern "C" void kernel_launch(void* const* d_in, const int* in_sizes, int n_in,
                              void* d_out, int out_size) {
    using namespace cfg;
    const float* values  = (const float*)d_in[0];
    const float* keys    = (const float*)d_in[1];
    const float* queries = (const float*)d_in[2];
    const float* Wq = (const float*)d_in[3];
    const float* bq = (const float*)d_in[4];
    const float* Wk = (const float*)d_in[5];
    const float* bk = (const float*)d_in[6];
    const float* Wv = (const float*)d_in[7];
    const float* bv = (const float*)d_in[8];
    const float* Wo = (const float*)d_in[9];
    const float* bo = (const float*)d_in[10];

    float* out   = (float*)d_out;
    float* attnw = out + BSD;

    float *wot, *bo2;
    uint4 *wot2_16h, *attn16h;
    cudaGetSymbolAddress((void**)&wot, g_wot);
    cudaGetSymbolAddress((void**)&bo2, g_bo2);
    cudaGetSymbolAddress((void**)&wot2_16h, g_wot2_16h);
    cudaGetSymbolAddress((void**)&attn16h, g_attn16h);

    constexpr int SMEM_CONV = 2 * 65536;
    constexpr int SMEM_H    = 3 * 32768;
    constexpr int SMEM_64   = 3 * 24576;
    cudaFuncSetAttribute(gemm_wot2,
                         cudaFuncAttributeMaxDynamicSharedMemorySize, SMEM_CONV);
    cudaFuncSetAttribute(gemm_qkvh,
                         cudaFuncAttributeMaxDynamicSharedMemorySize, SMEM_H);
    cudaFuncSetAttribute(gemm64h,
                         cudaFuncAttributeMaxDynamicSharedMemorySize, SMEM_64);
    cudaFuncSetAttribute(fused_attn,
                         cudaFuncAttributeMaxDynamicSharedMemorySize, SMEM_FA);

    // 1: Wo transpose (fp32, exact path for wot2)
    transpose_g<<<dim3(32, 32), dim3(32, 8)>>>(Wo, wot);
    // 2: weights -> fp16 planes
    wconv<<<dim3(16, 8, 3), 256>>>(Wq, Wk, Wv);
    // 3: inputs -> fp16 planes
    convert3<<<dim3(16, 64, 3), 256>>>(queries, keys, values);
    // 4: bo2 = bo@Wo + bo
    bo2_k<<<32, dim3(32, 16)>>>(bo, Wo);
    // 5: wot2 = (Wo@Wo)^T -> fp16 plane (bf16-split exact)
    gemm_wot2<<<dim3(8, 8), 256, SMEM_CONV>>>(wot, Wo, wot2_16h);
    // 6: merged QKV projections (all fp16; V^T planes in-epilogue)
    gemm_qkvh<<<dim3(8, 64, 3), 256, SMEM_H>>>(bq, bk, bv);
    // 7: fused attention (512 threads)
    fused_attn<<<dim3(64, 64), 512, SMEM_FA>>>(attnw);
    // 8: out-projection (fp16, 64x128 tiles)
    gemm64h<<<dim3(8, 128), 256, SMEM_64>>>(attn16h, 8192, wot2_16h, 1024,
                                            out, 1024, 16, bo2);
}

// round 17
// speedup vs baseline: 1.0743x; 1.0743x over previous
#include <cuda_runtime.h>
#include <cuda_bf16.h>
#include <cuda_fp16.h>
#include <math.h>
#include <stdint.h>

namespace cfg {
constexpr int B = 4, S = 2048, D = 1024, H = 16, DK = 64;
constexpr long long BSD = (long long)B * S * D;
constexpr long long SS  = (long long)S * S;
}

// ---------------------------------------------------------------------------
// Single-fp16 plane [chunk][row][u], unit stored at u ^ (row & 7).
// ---------------------------------------------------------------------------
__device__ float g_wot[1024 * 1024];
__device__ float g_bo2[1024];

__device__ uint4 g_xq16h[16LL * 8192 * 8];
__device__ uint4 g_xk16h[16LL * 8192 * 8];
__device__ uint4 g_xv16h[16LL * 8192 * 8];
__device__ uint4 g_wq16h[16LL * 1024 * 8];
__device__ uint4 g_wk16h[16LL * 1024 * 8];
__device__ uint4 g_wv16h[16LL * 1024 * 8];
__device__ uint4 g_wot2_16h[16LL * 1024 * 8];
__device__ uint4 g_attn16h[16LL * 8192 * 8];
__device__ uint4 g_q16h[16LL * 8192 * 8];
__device__ uint4 g_k16h[16LL * 8192 * 8];
__device__ uint4 g_vt16h[64LL * 32 * 64 * 8];

// ---------------------------------------------------------------------------
__device__ __forceinline__ uint32_t smem_u32(const void* p) {
    uint32_t a;
    asm("{ .reg .u64 t; cvta.to.shared.u64 t, %1; cvt.u32.u64 %0, t; }"
        : "=r"(a) : "l"(p));
    return a;
}
__device__ __forceinline__ void ldsm_x4(uint32_t addr, uint32_t r[4]) {
    asm volatile("ldmatrix.sync.aligned.m8n8.x4.shared.b16 {%0,%1,%2,%3}, [%4];"
                 : "=r"(r[0]), "=r"(r[1]), "=r"(r[2]), "=r"(r[3]) : "r"(addr));
}
__device__ __forceinline__ void mma_bf16(float* c, const uint32_t* a,
                                         uint32_t b0, uint32_t b1) {
    asm volatile(
        "mma.sync.aligned.m16n8k16.row.col.f32.bf16.bf16.f32 "
        "{%0,%1,%2,%3},{%4,%5,%6,%7},{%8,%9},{%0,%1,%2,%3};"
        : "+f"(c[0]), "+f"(c[1]), "+f"(c[2]), "+f"(c[3])
        : "r"(a[0]), "r"(a[1]), "r"(a[2]), "r"(a[3]), "r"(b0), "r"(b1));
}
__device__ __forceinline__ void mma_fp16(float* c, const uint32_t* a,
                                         uint32_t b0, uint32_t b1) {
    asm volatile(
        "mma.sync.aligned.m16n8k16.row.col.f32.f16.f16.f32 "
        "{%0,%1,%2,%3},{%4,%5,%6,%7},{%8,%9},{%0,%1,%2,%3};"
        : "+f"(c[0]), "+f"(c[1]), "+f"(c[2]), "+f"(c[3])
        : "r"(a[0]), "r"(a[1]), "r"(a[2]), "r"(a[3]), "r"(b0), "r"(b1));
}
__device__ __forceinline__ void cp16(uint32_t dst, const void* src) {
    asm volatile("cp.async.cg.shared.global [%0], [%1], 16;" :: "r"(dst), "l"(src));
}
__device__ __forceinline__ void cp_commit() {
    asm volatile("cp.async.commit_group;" ::: "memory");
}
template <int N>
__device__ __forceinline__ void cp_wait() {
    asm volatile("cp.async.wait_group %0;" :: "n"(N) : "memory");
}
__device__ __forceinline__ void stg_cs4(float* p, float a, float b, float c, float d) {
    asm volatile("st.global.cs.v4.f32 [%0], {%1,%2,%3,%4};"
                 :: "l"(p), "f"(a), "f"(b), "f"(c), "f"(d) : "memory");
}
#define SWZ(o) ((o) ^ (((o) >> 3) & 0x70))

__device__ __forceinline__ void split2(float a, float b, uint32_t& hi, uint32_t& lo) {
    __nv_bfloat16 ha = __float2bfloat16_rn(a);
    __nv_bfloat16 hb = __float2bfloat16_rn(b);
    __nv_bfloat16 la = __float2bfloat16_rn(a - __bfloat162float(ha));
    __nv_bfloat16 lb = __float2bfloat16_rn(b - __bfloat162float(hb));
    hi = (uint32_t)__bfloat16_as_ushort(ha) | ((uint32_t)__bfloat16_as_ushort(hb) << 16);
    lo = (uint32_t)__bfloat16_as_ushort(la) | ((uint32_t)__bfloat16_as_ushort(lb) << 16);
}
__device__ __forceinline__ uint32_t ph2(float a, float b) {
    __half2 h = __floats2half2_rn(a, b);
    return *reinterpret_cast<uint32_t*>(&h);
}
__device__ __forceinline__ void packh8(const float* v, uint4& o) {
    o.x = ph2(v[0], v[1]); o.y = ph2(v[2], v[3]);
    o.z = ph2(v[4], v[5]); o.w = ph2(v[6], v[7]);
}
__device__ __forceinline__ float2 uph2(uint32_t p) {
    __half2 h = *reinterpret_cast<__half2*>(&p);
    return __half22float2(h);
}

// Split-bf16 MMA (3 terms) over buffer AHI|ALO|BHI|BLO (128x128x64)
__device__ __forceinline__ void mma_buf(uint32_t base, int lane, int wm, int wn,
                                        float (&acc)[4][4][4]) {
    const int lrow = lane & 15, lkh = lane >> 4;
#pragma unroll
    for (int kk = 0; kk < 4; kk++) {
        const int kc = kk * 2 + lkh;
        uint32_t ahi[4][4], alo[4][4];
#pragma unroll
        for (int fm = 0; fm < 4; fm++) {
            uint32_t off = SWZ((uint32_t)((wm * 64 + fm * 16 + lrow) * 128 + kc * 16));
            ldsm_x4(base + off, ahi[fm]);
            ldsm_x4(base + 16384 + off, alo[fm]);
        }
        uint32_t bhi[2][4], blo[2][4];
#pragma unroll
        for (int fp = 0; fp < 2; fp++) {
            uint32_t off = SWZ((uint32_t)((wn * 32 + fp * 16 + lrow) * 128 + kc * 16));
            ldsm_x4(base + 32768 + off, bhi[fp]);
            ldsm_x4(base + 32768 + 16384 + off, blo[fp]);
        }
#pragma unroll
        for (int fm = 0; fm < 4; fm++)
#pragma unroll
            for (int fn = 0; fn < 4; fn++) {
                const int fp = fn >> 1, sel = fn & 1;
                mma_bf16(acc[fm][fn], ahi[fm], bhi[fp][sel], bhi[fp][sel + 2]);
                mma_bf16(acc[fm][fn], ahi[fm], blo[fp][sel], blo[fp][sel + 2]);
                mma_bf16(acc[fm][fn], alo[fm], bhi[fp][sel], bhi[fp][sel + 2]);
            }
    }
}

// Single-fp16 MMA over buffer A(16K)|B(16K) (128x128x64)
__device__ __forceinline__ void mma_buf1h(uint32_t base, int lane, int wm, int wn,
                                          float (&acc)[4][4][4]) {
    const int lrow = lane & 15, lkh = lane >> 4;
#pragma unroll
    for (int kk = 0; kk < 4; kk++) {
        const int kc = kk * 2 + lkh;
        uint32_t a[4][4];
#pragma unroll
        for (int fm = 0; fm < 4; fm++) {
            uint32_t off = SWZ((uint32_t)((wm * 64 + fm * 16 + lrow) * 128 + kc * 16));
            ldsm_x4(base + off, a[fm]);
        }
        uint32_t b[2][4];
#pragma unroll
        for (int fp = 0; fp < 2; fp++) {
            uint32_t off = SWZ((uint32_t)((wn * 32 + fp * 16 + lrow) * 128 + kc * 16));
            ldsm_x4(base + 16384 + off, b[fp]);
        }
#pragma unroll
        for (int fm = 0; fm < 4; fm++)
#pragma unroll
            for (int fn = 0; fn < 4; fn++) {
                const int fp = fn >> 1, sel = fn & 1;
                mma_fp16(acc[fm][fn], a[fm], b[fp][sel], b[fp][sel + 2]);
            }
    }
}

// Single-fp16 MMA over buffer A(8K: 64 rows)|B(16K) (64x128x64)
__device__ __forceinline__ void mma_buf64h(uint32_t base, int lane, int wm, int wn,
                                           float (&acc)[2][4][4]) {
    const int lrow = lane & 15, lkh = lane >> 4;
#pragma unroll
    for (int kk = 0; kk < 4; kk++) {
        const int kc = kk * 2 + lkh;
        uint32_t a[2][4];
#pragma unroll
        for (int fm = 0; fm < 2; fm++) {
            uint32_t off = SWZ((uint32_t)((wm * 32 + fm * 16 + lrow) * 128 + kc * 16));
            ldsm_x4(base + off, a[fm]);
        }
        uint32_t b[2][4];
#pragma unroll
        for (int fp = 0; fp < 2; fp++) {
            uint32_t off = SWZ((uint32_t)((wn * 32 + fp * 16 + lrow) * 128 + kc * 16));
            ldsm_x4(base + 8192 + off, b[fp]);
        }
#pragma unroll
        for (int fm = 0; fm < 2; fm++)
#pragma unroll
            for (int fn = 0; fn < 4; fn++) {
                const int fp = fn >> 1, sel = fn & 1;
                mma_fp16(acc[fm][fn], a[fm], b[fp][sel], b[fp][sel + 2]);
            }
    }
}

// ---------------------------------------------------------------------------
// wot2 = (Wo@Wo)^T via bf16 split from fp32 (exact path); fp16 plane out.
// ---------------------------------------------------------------------------
__global__ __launch_bounds__(256, 1) void gemm_wot2(
    const float* __restrict__ A, const float* __restrict__ Bt,
    uint4* __restrict__ C16h) {
    extern __shared__ __align__(1024) char smem[];
    constexpr int BUFSZ = 65536;
    const uint32_t sb = smem_u32(smem);
    const int tid = threadIdx.x, lane = tid & 31, w = tid >> 5;
    const int wm = w & 1, wn = w >> 1;
    const long long rowBase = (long long)blockIdx.y * 128;
    const int colBase = blockIdx.x * 128;
    float acc[4][4][4] = {};

    const int rA = tid >> 4, qA = tid & 15;
    float4 ra[8], rb[8];
    auto loadAB = [&](int c) {
#pragma unroll
        for (int i = 0; i < 8; i++)
            ra[i] = *(const float4*)(A + (rowBase + rA + i * 16) * 1024 +
                                     c * 64 + qA * 4);
#pragma unroll
        for (int i = 0; i < 8; i++)
            rb[i] = *(const float4*)(Bt + (long long)(colBase + rA + i * 16) * 1024 +
                                     c * 64 + qA * 4);
    };
    auto store = [&](int buf) {
        char* base = smem + buf * BUFSZ;
#pragma unroll
        for (int i = 0; i < 8; i++) {
            uint32_t h01, l01, h23, l23;
            split2(ra[i].x, ra[i].y, h01, l01);
            split2(ra[i].z, ra[i].w, h23, l23);
            uint32_t off = SWZ((uint32_t)((rA + i * 16) * 128 + qA * 8));
            *(uint2*)(base + off) = make_uint2(h01, h23);
            *(uint2*)(base + 16384 + off) = make_uint2(l01, l23);
        }
#pragma unroll
        for (int i = 0; i < 8; i++) {
            uint32_t h01, l01, h23, l23;
            split2(rb[i].x, rb[i].y, h01, l01);
            split2(rb[i].z, rb[i].w, h23, l23);
            uint32_t off = SWZ((uint32_t)((rA + i * 16) * 128 + qA * 8));
            *(uint2*)(base + 32768 + off) = make_uint2(h01, h23);
            *(uint2*)(base + 49152 + off) = make_uint2(l01, l23);
        }
    };
    loadAB(0); store(0);
    __syncthreads();
    for (int c = 0; c < 16; c++) {
        const int b = c & 1;
        if (c + 1 < 16) loadAB(c + 1);
        mma_buf(sb + b * BUFSZ, lane, wm, wn, acc);
        if (c + 1 < 16) store(1 - b);
        __syncthreads();
    }
    __syncthreads();

    float* stage = (float*)smem;  // 128 x 132
    const int rl0 = wm * 64 + (lane >> 2), cl0 = wn * 32 + (lane & 3) * 2;
#pragma unroll
    for (int fm = 0; fm < 4; fm++)
#pragma unroll
        for (int fn = 0; fn < 4; fn++) {
            int r = rl0 + fm * 16, c = cl0 + fn * 8;
            stage[r * 132 + c] = acc[fm][fn][0];
            stage[r * 132 + c + 1] = acc[fm][fn][1];
            stage[(r + 8) * 132 + c] = acc[fm][fn][2];
            stage[(r + 8) * 132 + c + 1] = acc[fm][fn][3];
        }
    __syncthreads();
#pragma unroll
    for (int i = 0; i < 8; i++) {
        int e = tid + i * 256, r = e >> 4, u16 = e & 15;
        float v[8];
#pragma unroll
        for (int j = 0; j < 8; j++) v[j] = stage[r * 132 + u16 * 8 + j];
        uint4 hv;
        packh8(v, hv);
        long long chunk = (colBase >> 6) + (u16 >> 3);
        int uu = (u16 & 7) ^ (r & 7);
        C16h[(chunk * 1024 + rowBase + r) * 8 + uu] = hv;
    }
}

// ---------------------------------------------------------------------------
// Merged QKV GEMM, all single-fp16. op = blockIdx.z. grid(8, 64, 3).
// op 0/1: fp16 plane out; op 2: V^T planes in-epilogue.
// ---------------------------------------------------------------------------
__global__ __launch_bounds__(256, 2) void gemm_qkvh(
    const float* __restrict__ bq, const float* __restrict__ bk,
    const float* __restrict__ bv) {
    extern __shared__ __align__(1024) char smem[];
    constexpr int BUFSZ = 32768;
    const uint32_t sb = smem_u32(smem);
    const int tid = threadIdx.x, lane = tid & 31, w = tid >> 5;
    const int wm = w & 1, wn = w >> 1;
    const int op = blockIdx.z;
    const uint4* A16h = op == 0 ? g_xq16h : (op == 1 ? g_xk16h : g_xv16h);
    const uint4* B16h = op == 0 ? g_wq16h : (op == 1 ? g_wk16h : g_wv16h);
    const float* bias = op == 0 ? bq : (op == 1 ? bk : bv);
    const long long rowBase = (long long)blockIdx.y * 128;
    const int colBase = blockIdx.x * 128;
    float acc[4][4][4] = {};

    auto issue = [&](int c, int buf) {
        uint32_t base = sb + buf * BUFSZ;
#pragma unroll
        for (int i = 0; i < 4; i++) {
            int e = tid + i * 256, r = e >> 3, j = e & 7;
            cp16(base + r * 128 + j * 16,
                 A16h + ((long long)c * 8192 + rowBase + r) * 8 + j);
        }
#pragma unroll
        for (int i = 0; i < 4; i++) {
            int e = tid + i * 256, r = e >> 3, j = e & 7;
            cp16(base + 16384 + r * 128 + j * 16,
                 B16h + ((long long)c * 1024 + colBase + r) * 8 + j);
        }
        cp_commit();
    };
    issue(0, 0);
    issue(1, 1);
    for (int c = 0; c < 16; c++) {
        if (c + 1 < 16) cp_wait<1>(); else cp_wait<0>();
        __syncthreads();
        mma_buf1h(sb + (c % 3) * BUFSZ, lane, wm, wn, acc);
        if (c + 2 < 16) issue(c + 2, (c + 2) % 3);
    }
    __syncthreads();

    float* stage = (float*)smem;  // 128 x 132
    const int rl0 = wm * 64 + (lane >> 2), cl0 = wn * 32 + (lane & 3) * 2;
#pragma unroll
    for (int fm = 0; fm < 4; fm++)
#pragma unroll
        for (int fn = 0; fn < 4; fn++) {
            int r = rl0 + fm * 16, c = cl0 + fn * 8;
            stage[r * 132 + c] = acc[fm][fn][0];
            stage[r * 132 + c + 1] = acc[fm][fn][1];
            stage[(r + 8) * 132 + c] = acc[fm][fn][2];
            stage[(r + 8) * 132 + c + 1] = acc[fm][fn][3];
        }
    __syncthreads();

    if (op != 2) {
        uint4* C16h = op == 0 ? g_q16h : g_k16h;
#pragma unroll
        for (int i = 0; i < 8; i++) {
            int e = tid + i * 256, r = e >> 4, u16 = e & 15;
            int gc = colBase + u16 * 8;
            float v[8];
#pragma unroll
            for (int j = 0; j < 8; j++)
                v[j] = stage[r * 132 + u16 * 8 + j] + bias[gc + j];
            uint4 hv;
            packh8(v, hv);
            long long chunk = (colBase >> 6) + (u16 >> 3);
            int uu = (u16 & 7) ^ (r & 7);
            C16h[(chunk * 8192 + rowBase + r) * 8 + uu] = hv;
        }
    } else {
        const int b = (int)(rowBase >> 11);
        const int scb = ((int)rowBase & 2047) >> 6;
#pragma unroll
        for (int i = 0; i < 8; i++) {
            int e = tid + i * 256;
            int hh = e >> 10, p = (e >> 9) & 1, dk = (e >> 3) & 63, u = e & 7;
            int col = hh * 64 + dk;
            float bb = bias[colBase + col];
            float v[8];
#pragma unroll
            for (int j = 0; j < 8; j++)
                v[j] = stage[(p * 64 + u * 8 + j) * 132 + col] + bb;
            uint4 hv;
            packh8(v, hv);
            long long z = (long long)b * 16 + (colBase >> 6) + hh;
            g_vt16h[((z * 32 + scb + p) * 64 + dk) * 8 + (u ^ (dk & 7))] = hv;
        }
    }
}

// ---------------------------------------------------------------------------
// Single-fp16 GEMM, tile 64x128. grid(8, 128).
// ---------------------------------------------------------------------------
__global__ __launch_bounds__(256, 2) void gemm64h(
    const uint4* __restrict__ A16h, long long rowsA,
    const uint4* __restrict__ B16h, long long rowsB,
    float* __restrict__ C, int ldc, int nch, const float* __restrict__ bias) {
    extern __shared__ __align__(1024) char smem[];
    constexpr int BUFSZ = 24576;
    const uint32_t sb = smem_u32(smem);
    const int tid = threadIdx.x, lane = tid & 31, w = tid >> 5;
    const int wm = w & 1, wn = w >> 1;
    const long long rowBase = (long long)blockIdx.y * 64;
    const int colBase = blockIdx.x * 128;
    float acc[2][4][4] = {};

    auto issue = [&](int c, int buf) {
        uint32_t base = sb + buf * BUFSZ;
#pragma unroll
        for (int i = 0; i < 2; i++) {
            int e = tid + i * 256, r = e >> 3, j = e & 7;
            cp16(base + r * 128 + j * 16,
                 A16h + ((long long)c * rowsA + rowBase + r) * 8 + j);
        }
#pragma unroll
        for (int i = 0; i < 4; i++) {
            int e = tid + i * 256, r = e >> 3, j = e & 7;
            cp16(base + 8192 + r * 128 + j * 16,
                 B16h + ((long long)c * rowsB + colBase + r) * 8 + j);
        }
        cp_commit();
    };
    issue(0, 0);
    issue(1, 1);
    for (int c = 0; c < nch; c++) {
        if (c + 1 < nch) cp_wait<1>(); else cp_wait<0>();
        __syncthreads();
        mma_buf64h(sb + (c % 3) * BUFSZ, lane, wm, wn, acc);
        if (c + 2 < nch) issue(c + 2, (c + 2) % 3);
    }

    const long long erow = rowBase + wm * 32 + (lane >> 2);
    const int ecol = colBase + wn * 32 + (lane & 3) * 2;
#pragma unroll
    for (int fm = 0; fm < 2; fm++)
#pragma unroll
        for (int fn = 0; fn < 4; fn++) {
            int cc = ecol + fn * 8;
            float b0 = bias ? bias[cc] : 0.f;
            float b1 = bias ? bias[cc + 1] : 0.f;
            long long r0 = erow + fm * 16;
            *(float2*)(C + r0 * ldc + cc) =
                make_float2(acc[fm][fn][0] + b0, acc[fm][fn][1] + b1);
            *(float2*)(C + (r0 + 8) * ldc + cc) =
                make_float2(acc[fm][fn][2] + b0, acc[fm][fn][3] + b1);
        }
}

// ---------------------------------------------------------------------------
// Fused attention (8 warps). CTA = 32 Q-rows x 2048 K, one (b,h).
// PV warps: (wm2, wn2 in {0,1}, kh in {0,1}) each 16x32 over half-K;
// halves summed once at the end. 12 ldsm / 16 MMA per warp per chunk.
// ---------------------------------------------------------------------------
#define OFF_E 0            // 32 chunks x 32 rows x 128B = 131072
#define OFF_K 131072       // 3 bufs x (K 16384 + V 16384)
#define OFF_SUM 229376     // 8 x 32 floats
#define OFF_INV 230400     // 32 floats
#define SMEM_FA 230528

__global__ __launch_bounds__(256, 1) void fused_attn(float* __restrict__ attnw) {
    extern __shared__ __align__(1024) char smem[];
    const uint32_t sb = smem_u32(smem);
    const int tid = threadIdx.x, lane = tid & 31, w = tid >> 5;
    const int lrow = lane & 15, lkh = lane >> 4;
    const int rb = blockIdx.x, z = blockIdx.y;
    const int b = z >> 4, h = z & 15;
    const long long qrow = (long long)b * 2048 + rb * 32;
    float* abz = attnw + (long long)z * cfg::SS;

    // Q staged through buf0's K area, fragments hoisted
    {
        int r = tid >> 3, j = tid & 7;
        cp16(sb + OFF_K + r * 128 + j * 16,
             g_q16h + ((long long)h * 8192 + qrow + r) * 8 + j);
        cp_commit();
    }
    cp_wait<0>();
    __syncthreads();
    uint32_t a_q[2][4][4];
#pragma unroll
    for (int kk = 0; kk < 4; kk++)
#pragma unroll
        for (int fm = 0; fm < 2; fm++) {
            uint32_t off = SWZ((uint32_t)((fm * 16 + lrow) * 128 + (kk * 2 + lkh) * 16));
            ldsm_x4(sb + OFF_K + off, a_q[fm][kk]);
        }
    __syncthreads();

    auto issueKV = [&](int c, int buf) {
#pragma unroll
        for (int i = 0; i < 4; i++) {
            int e = tid + i * 256, r = e >> 3, j = e & 7;
            cp16(sb + OFF_K + buf * 32768 + r * 128 + j * 16,
                 g_k16h + ((long long)h * 8192 + (long long)b * 2048 + c * 128 + r) * 8 + j);
        }
#pragma unroll
        for (int i = 0; i < 4; i++) {
            int e = tid + i * 256, sc = e >> 9, r = (e >> 3) & 63, j = e & 7;
            cp16(sb + OFF_K + buf * 32768 + 16384 + sc * 8192 + r * 128 + j * 16,
                 g_vt16h + (((long long)z * 32 + c * 2 + sc) * 64 + r) * 8 + j);
        }
        cp_commit();
    };
    issueKV(0, 0);
    issueKV(1, 1);

    // PV mapping: 16x32 tile over half-K
    const int wm2 = w & 1, wn2 = (w >> 1) & 1, kh = w >> 2;
    float acc_pv[4][4] = {};
    float rs[2][2] = {};

    for (int c = 0; c < 16; c++) {
        const int buf = c % 3;
        if (c + 1 < 16) cp_wait<1>(); else cp_wait<0>();
        __syncthreads();
        if (c + 2 < 16) issueKV(c + 2, (c + 2) % 3);

        // ---- scores: S = Q(32x64) @ K_chunk(128x64)^T (warp: 16 K-cols) ----
        float acc_s[2][2][4] = {};
#pragma unroll
        for (int kk = 0; kk < 4; kk++) {
            uint32_t bk[4];
            uint32_t off = SWZ((uint32_t)((w * 16 + lrow) * 128 + (kk * 2 + lkh) * 16));
            ldsm_x4(sb + OFF_K + buf * 32768 + off, bk);
#pragma unroll
            for (int fm = 0; fm < 2; fm++)
#pragma unroll
                for (int fn = 0; fn < 2; fn++)
                    mma_fp16(acc_s[fm][fn], a_q[fm][kk], bk[fn], bk[fn + 2]);
        }

        // ---- exp -> E smem, rowsum ----
#pragma unroll
        for (int fm = 0; fm < 2; fm++) {
            int r0 = fm * 16 + (lane >> 2);
#pragma unroll
            for (int fn = 0; fn < 2; fn++) {
                int col = w * 16 + fn * 8 + (lane & 3) * 2;
                float e0 = __expf(acc_s[fm][fn][0] * 0.125f);
                float e1 = __expf(acc_s[fm][fn][1] * 0.125f);
                float e2 = __expf(acc_s[fm][fn][2] * 0.125f);
                float e3 = __expf(acc_s[fm][fn][3] * 0.125f);
                int sub = col >> 6, cu = (col & 63) >> 3, cb = (col & 7) * 2;
                uint32_t bc = OFF_E + (c * 2 + sub) * 4096;
                *(uint32_t*)(smem + bc + r0 * 128 + ((cu ^ (r0 & 7)) << 4) + cb) =
                    ph2(e0, e1);
                *(uint32_t*)(smem + bc + (r0 + 8) * 128 +
                             ((cu ^ ((r0 + 8) & 7)) << 4) + cb) = ph2(e2, e3);
                rs[fm][0] += e0 + e1;
                rs[fm][1] += e2 + e3;
            }
        }
        __syncthreads();

        // ---- PV: warp tile 16x32 over its half-K (64) ----
#pragma unroll
        for (int kk2 = 0; kk2 < 4; kk2++) {
            uint32_t ae[4], bv0[4], bv1[4];
            int kc = kk2 * 2 + lkh;
            uint32_t offa = SWZ((uint32_t)((wm2 * 16 + lrow) * 128 + kc * 16));
            ldsm_x4(sb + OFF_E + (c * 2 + kh) * 4096 + offa, ae);
            uint32_t vb = sb + OFF_K + buf * 32768 + 16384 + kh * 8192;
            uint32_t offb0 = SWZ((uint32_t)((wn2 * 32 + lrow) * 128 + kc * 16));
            ldsm_x4(vb + offb0, bv0);
            uint32_t offb1 = SWZ((uint32_t)((wn2 * 32 + 16 + lrow) * 128 + kc * 16));
            ldsm_x4(vb + offb1, bv1);
            mma_fp16(acc_pv[0], ae, bv0[0], bv0[2]);
            mma_fp16(acc_pv[1], ae, bv0[1], bv0[3]);
            mma_fp16(acc_pv[2], ae, bv1[0], bv1[2]);
            mma_fp16(acc_pv[3], ae, bv1[1], bv1[3]);
        }
    }

    // ---- kh=1 halves -> stage2 ----
    float* stage2 = (float*)(smem + OFF_K + 16384);  // 32 x 64
    if (kh == 1) {
        int rr = wm2 * 16 + (lane >> 2);
#pragma unroll
        for (int fn = 0; fn < 4; fn++) {
            int cc = wn2 * 32 + fn * 8 + (lane & 3) * 2;
            stage2[rr * 64 + cc] = acc_pv[fn][0];
            stage2[rr * 64 + cc + 1] = acc_pv[fn][1];
            stage2[(rr + 8) * 64 + cc] = acc_pv[fn][2];
            stage2[(rr + 8) * 64 + cc + 1] = acc_pv[fn][3];
        }
    }

    // ---- rowsum reduce -> inv ----
    float* sums = (float*)(smem + OFF_SUM);
    float* inv_s = (float*)(smem + OFF_INV);
#pragma unroll
    for (int fm = 0; fm < 2; fm++) {
        float s0 = rs[fm][0], s1 = rs[fm][1];
        s0 += __shfl_xor_sync(~0u, s0, 1); s0 += __shfl_xor_sync(~0u, s0, 2);
        s1 += __shfl_xor_sync(~0u, s1, 1); s1 += __shfl_xor_sync(~0u, s1, 2);
        if ((lane & 3) == 0) {
            int r0 = fm * 16 + (lane >> 2);
            sums[w * 32 + r0] = s0;
            sums[w * 32 + r0 + 8] = s1;
        }
    }
    __syncthreads();
    if (tid < 32) {
        float s = 0.f;
#pragma unroll
        for (int i = 0; i < 8; i++) s += sums[i * 32 + tid];
        inv_s[tid] = 1.f / s;
    }
    __syncthreads();

    // ---- combine halves, scale, stage attn tile (kh=0 warps) ----
    if (kh == 0) {
        int rr = wm2 * 16 + (lane >> 2);
        float s0 = inv_s[rr], s1 = inv_s[rr + 8];
        float* stage = (float*)(smem + OFF_K);  // 32 x 68
#pragma unroll
        for (int fn = 0; fn < 4; fn++) {
            int cc = wn2 * 32 + fn * 8 + (lane & 3) * 2;
            stage[rr * 68 + cc] =
                (acc_pv[fn][0] + stage2[rr * 64 + cc]) * s0;
            stage[rr * 68 + cc + 1] =
                (acc_pv[fn][1] + stage2[rr * 64 + cc + 1]) * s0;
            stage[(rr + 8) * 68 + cc] =
                (acc_pv[fn][2] + stage2[(rr + 8) * 64 + cc]) * s1;
            stage[(rr + 8) * 68 + cc + 1] =
                (acc_pv[fn][3] + stage2[(rr + 8) * 64 + cc + 1]) * s1;
        }
    }
    __syncthreads();

    // ---- normalized fp32 attn_weights (32 x 2048), streaming ----
    {
        int r = tid >> 3, u = tid & 7;
        float sc = inv_s[r];
        float* dst_row = abz + (long long)(rb * 32 + r) * 2048;
        uint32_t src_ru = OFF_E + r * 128 + ((u ^ (r & 7)) << 4);
#pragma unroll 4
        for (int cc = 0; cc < 32; cc++) {
            uint4 hv = *(uint4*)(smem + src_ru + cc * 4096);
            float2 v0 = uph2(hv.x), v1 = uph2(hv.y);
            float2 v2 = uph2(hv.z), v3 = uph2(hv.w);
            float* dst = dst_row + cc * 64 + u * 8;
            stg_cs4(dst, v0.x * sc, v0.y * sc, v1.x * sc, v1.y * sc);
            stg_cs4(dst + 4, v2.x * sc, v2.y * sc, v3.x * sc, v3.y * sc);
        }
    }

    // ---- fp16 attn plane (32 x 64, chunk = h) ----
    {
        int r = tid >> 3, u = tid & 7;
        float* stage = (float*)(smem + OFF_K);
        float v[8];
#pragma unroll
        for (int j = 0; j < 8; j++) v[j] = stage[r * 68 + u * 8 + j];
        uint4 hv;
        packh8(v, hv);
        int uu = u ^ (r & 7);
        long long grow = (long long)b * 2048 + rb * 32 + r;
        g_attn16h[((long long)h * 8192 + grow) * 8 + uu] = hv;
    }
}

// ---------------------------------------------------------------------------
// Prep kernels
// ---------------------------------------------------------------------------
__global__ void wconv(const float* __restrict__ Wq, const float* __restrict__ Wk,
                      const float* __restrict__ Wv) {
    __shared__ float t2[128][65];
    const int cc = blockIdx.x, rb = blockIdx.y, op = blockIdx.z;
    const float* W = op == 0 ? Wq : (op == 1 ? Wk : Wv);
    uint4* O = op == 0 ? g_wq16h : (op == 1 ? g_wk16h : g_wv16h);
    const int tid = threadIdx.x;
#pragma unroll
    for (int i = 0; i < 32; i++) {
        int e = tid + i * 256, wr = e >> 7, wc = e & 127;
        t2[wc][wr] = W[(cc * 64 + wr) * 1024 + rb * 128 + wc];
    }
    __syncthreads();
#pragma unroll
    for (int i = 0; i < 4; i++) {
        int e = tid + i * 256, r = e >> 3, u = e & 7;
        float v[8];
#pragma unroll
        for (int j = 0; j < 8; j++) v[j] = t2[r][u * 8 + j];
        uint4 hv;
        packh8(v, hv);
        O[((long long)cc * 1024 + rb * 128 + r) * 8 + (u ^ (r & 7))] = hv;
    }
}

__global__ void convert3(const float* __restrict__ q, const float* __restrict__ k,
                         const float* __restrict__ v) {
    const int chunk = blockIdx.x, op = blockIdx.z;
    const float* X = op == 0 ? q : (op == 1 ? k : v);
    uint4* O = op == 0 ? g_xq16h : (op == 1 ? g_xk16h : g_xv16h);
    const long long rb = (long long)blockIdx.y * 128;
    const int tid = threadIdx.x;
#pragma unroll
    for (int i = 0; i < 4; i++) {
        int e = tid + i * 256, r = e >> 3, u = e & 7;
        const float* src = X + (rb + r) * 1024 + chunk * 64 + u * 8;
        float v8[8];
        *(float4*)(v8) = *(const float4*)(src);
        *(float4*)(v8 + 4) = *(const float4*)(src + 4);
        uint4 hv;
        packh8(v8, hv);
        O[((long long)chunk * 8192 + rb + r) * 8 + (u ^ (r & 7))] = hv;
    }
}

__global__ void transpose_g(const float* __restrict__ in, float* __restrict__ out) {
    __shared__ float tile[32][33];
    const int bx = blockIdx.x * 32, by = blockIdx.y * 32;
    const int tx = threadIdx.x, ty = threadIdx.y;
#pragma unroll
    for (int i = 0; i < 32; i += 8)
        tile[ty + i][tx] = in[(long long)(by + ty + i) * 1024 + bx + tx];
    __syncthreads();
#pragma unroll
    for (int i = 0; i < 32; i += 8)
        out[(long long)(bx + ty + i) * 1024 + by + tx] = tile[tx][ty + i];
}

__global__ void bo2_k(const float* __restrict__ bo, const float* __restrict__ Wo) {
    __shared__ float red[16][32];
    const int j = blockIdx.x * 32 + threadIdx.x;
    const int ty = threadIdx.y;
    float s = 0.f;
#pragma unroll 16
    for (int k = ty * 64; k < ty * 64 + 64; k++)
        s += bo[k] * Wo[k * 1024 + j];
    red[ty][threadIdx.x] = s;
    __syncthreads();
    if (ty == 0) {
        float t = bo[j];
#pragma unroll
        for (int i = 0; i < 16; i++) t += red[i][threadIdx.x];
        g_bo2[j] = t;
    }
}

extern "C" void kernel_launch(void* const* d_in, const int* in_sizes, int n_in,
                              void* d_out, int out_size) {
    using namespace cfg;
    const float* values  = (const float*)d_in[0];
    const float* keys    = (const float*)d_in[1];
    const float* queries = (const float*)d_in[2];
    const float* Wq = (const float*)d_in[3];
    const float* bq = (const float*)d_in[4];
    const float* Wk = (const float*)d_in[5];
    const float* bk = (const float*)d_in[6];
    const float* Wv = (const float*)d_in[7];
    const float* bv = (const float*)d_in[8];
    const float* Wo = (const float*)d_in[9];
    const float* bo = (const float*)d_in[10];

    float* out   = (float*)d_out;
    float* attnw = out + BSD;

    float *wot, *bo2;
    uint4 *wot2_16h, *attn16h;
    cudaGetSymbolAddress((void**)&wot, g_wot);
    cudaGetSymbolAddress((void**)&bo2, g_bo2);
    cudaGetSymbolAddress((void**)&wot2_16h, g_wot2_16h);
    cudaGetSymbolAddress((void**)&attn16h, g_attn16h);

    constexpr int SMEM_CONV = 2 * 65536;
    constexpr int SMEM_H    = 3 * 32768;
    constexpr int SMEM_64   = 3 * 24576;
    cudaFuncSetAttribute(gemm_wot2,
                         cudaFuncAttributeMaxDynamicSharedMemorySize, SMEM_CONV);
    cudaFuncSetAttribute(gemm_qkvh,
                         cudaFuncAttributeMaxDynamicSharedMemorySize, SMEM_H);
    cudaFuncSetAttribute(gemm64h,
                         cudaFuncAttributeMaxDynamicSharedMemorySize, SMEM_64);
    cudaFuncSetAttribute(fused_attn,
                         cudaFuncAttributeMaxDynamicSharedMemorySize, SMEM_FA);

    // 1: Wo transpose (fp32, exact path for wot2)
    transpose_g<<<dim3(32, 32), dim3(32, 8)>>>(Wo, wot);
    // 2: weights -> fp16 planes
    wconv<<<dim3(16, 8, 3), 256>>>(Wq, Wk, Wv);
    // 3: inputs -> fp16 planes
    convert3<<<dim3(16, 64, 3), 256>>>(queries, keys, values);
    // 4: bo2 = bo@Wo + bo
    bo2_k<<<32, dim3(32, 16)>>>(bo, Wo);
    // 5: wot2 = (Wo@Wo)^T -> fp16 plane (bf16-split exact)
    gemm_wot2<<<dim3(8, 8), 256, SMEM_CONV>>>(wot, Wo, wot2_16h);
    // 6: merged QKV projections (all fp16; V^T planes in-epilogue)
    gemm_qkvh<<<dim3(8, 64, 3), 256, SMEM_H>>>(bq, bk, bv);
    // 7: fused attention (8 warps, split-K PV)
    fused_attn<<<dim3(64, 64), 256, SMEM_FA>>>(attnw);
    // 8: out-projection (fp16, 64x128 tiles)
    gemm64h<<<dim3(8, 128), 256, SMEM_64>>>(attn16h, 8192, wot2_16h, 1024,
                                            out, 1024, 16, bo2);
}